// round 15
// baseline (speedup 1.0000x reference)
#include <cuda_runtime.h>

// Problem constants
#define NCTA   128
#define TPB    256
#define NB     512
#define BT     4       // batch elements per CTA
#define NC     184     // cities
#define HH     32      // hidden
#define IND    14      // in_dim
#define DD     15      // in_dim + 1
#define NPRED  24
#define NHIST  24
#define NFEAT  13      // in_dim - 1
#define FTOT   48      // hist + pred

// Global scratch (per-CTA private; fwd y0 in [city][q][b][dk] layout, 128 f/city)
__device__ float g_y0[(size_t)NCTA * NC * 128];

// Shared memory layout (float offsets)
#define OFF_X2   0        // 184*15*4 = 11040  x tile OLD layout [c][k15][b] (MLP/GRU)
#define OFF_XL   11040    // 184*64   = 11776  x tile LSTM layout [c][q4][b][dk]
#define OFF_Y0B  22816    // 184*128  = 23552  bwd y0 [c][q8][b][dk]
#define OFF_XIN  46368    // 2dir*2buf*128     staged fwd y0 [q8][b][dk]
#define OFF_G    46880    // 2*4*128  = 1024   ACTIVATED gates [dir][b][row]
#define OFF_H    47904    // 4ld*128  = 512    h state [ld][q8][b][dk]
#define OFF_XN   48416    // 184*4    = 736
#define OFF_GX   49152    // 384
#define OFF_GH   49536    // 1536
#define OFF_U    51072    // 64
#define SMEM_FLOATS 51136 // 204,544 bytes

typedef unsigned long long u64;

__device__ __forceinline__ u64 pk2(float w) {
    u64 r; asm("mov.b64 %0, {%1, %1};" : "=l"(r) : "f"(w)); return r;
}
__device__ __forceinline__ u64 pack2(float a, float b) {
    u64 r; asm("mov.b64 %0, {%1, %2};" : "=l"(r) : "f"(a), "f"(b)); return r;
}
__device__ __forceinline__ void ffma2(u64& a, u64 x, u64 w) {
    asm("fma.rn.f32x2 %0, %1, %2, %0;" : "+l"(a) : "l"(x), "l"(w));
}
__device__ __forceinline__ u64 addx2(u64 a, u64 b) {
    u64 r; asm("add.rn.f32x2 %0, %1, %2;" : "=l"(r) : "l"(a), "l"(b)); return r;
}
__device__ __forceinline__ float2 unpk(u64 a) {
    float2 f; asm("mov.b64 {%0, %1}, %2;" : "=f"(f.x), "=f"(f.y) : "l"(a)); return f;
}
__device__ __forceinline__ float tanha(float x) {
    float r; asm("tanh.approx.f32 %0, %1;" : "=f"(r) : "f"(x)); return r;
}
__device__ __forceinline__ float sigf(float x) {
    return fmaf(0.5f, tanha(0.5f * x), 0.5f);
}
// per-direction named barrier (128 threads)
__device__ __forceinline__ void dbar(int dir) {
    asm volatile("bar.sync %0, %1;" :: "r"(1 + dir), "r"(128) : "memory");
}

// LSTM-layout index: k -> quad/byte position for batch b
__device__ __forceinline__ int lidx(int k, int b) {
    return (k >> 2) * 16 + b * 4 + (k & 3);
}

__global__ void __launch_bounds__(TPB, 1)
bilstm_kernel(const float* __restrict__ rain_hist,
              const float* __restrict__ feature,
              const float* __restrict__ h0,
              const float* __restrict__ c0,
              const float* __restrict__ W_mlp,
              const float* __restrict__ b_mlp,
              const float* __restrict__ Wih_g,
              const float* __restrict__ Whh_g,
              const float* __restrict__ b_ih_g,
              const float* __restrict__ b_hh_g,
              const float* __restrict__ Wih0,
              const float* __restrict__ Whh0,
              const float* __restrict__ b0,
              const float* __restrict__ Wih1,
              const float* __restrict__ Whh1,
              const float* __restrict__ b1,
              const float* __restrict__ W_fc,
              const float* __restrict__ b_fc,
              float* __restrict__ out)
{
    extern __shared__ float sm[];
    float* sX2  = sm + OFF_X2;
    float* sXL  = sm + OFF_XL;
    float* sY0B = sm + OFF_Y0B;
    float* sXin = sm + OFF_XIN;
    float* sG   = sm + OFF_G;
    float* sH   = sm + OFF_H;
    float* sXN  = sm + OFF_XN;
    float* sGX  = sm + OFF_GX;
    float* sGH  = sm + OFF_GH;
    float* sU   = sm + OFF_U;

    const int tid = threadIdx.x;
    const int cta = blockIdx.x;
    const int bg  = cta * BT;

    const int dirg = tid >> 7;          // direction
    // L1 gate mapping: 2 rows x 2 batches
    const int bh   = tid & 1;
    const int rp   = (tid >> 1) & 63;
    const int r0   = rp * 2;
    // L0 gate mapping: 4 rows x 1 batch
    const int r4   = (tid >> 2) & 31;   // row quad -> rows r4*4..r4*4+3
    const int bq   = tid & 3;           // batch
    // update mapping
    const int bu   = (tid >> 5) & 3;
    const int ju   = tid & 31;
    const int loc  = tid & 127;

    const float wfc = W_fc[ju];
    const float bfc = b_fc[0];
    const bool isG0 = ((r4 >> 3) == 2);   // L0 thread's gate class == g
    const bool isG1 = ((r0 >> 5) == 2);   // L1 thread's gate class == g

    // c-state in update-thread registers
    float cL0 = c0[((size_t)dirg * NB + bg + bu) * HH + ju];
    float cL1 = c0[((size_t)(2 + dirg) * NB + bg + bu) * HH + ju];

    // ---- initial h, xn, pad slot ----
    for (int e = tid; e < 4 * HH * BT; e += TPB) {
        int ld = e >> 7, k = (e >> 2) & 31, b = e & 3;
        sH[ld * 128 + lidx(k, b)] = h0[((size_t)ld * NB + bg + b) * HH + k];
    }
    for (int e = tid; e < NC * BT; e += TPB) {
        int c = e >> 2, b = e & 3;
        sXN[c * BT + b] = rain_hist[((size_t)(bg + b) * NHIST + (NHIST - 1)) * NC + c];
        sXL[c * 64 + lidx(15, b)] = 0.0f;    // zero pad, never overwritten
    }
    __syncthreads();

    float* gy0cta = g_y0 + (size_t)cta * NC * 128;

    for (int t = 0; t < NPRED; ++t) {
        // ============ Phase 1: build both x tiles ============
        for (int e = tid; e < NC * NFEAT * BT; e += TPB) {
            int b = e / (NC * NFEAT);
            int rem = e - b * (NC * NFEAT);
            int c = rem / NFEAT;
            int kk = rem - c * NFEAT;
            float v = feature[(((size_t)(bg + b) * FTOT + NHIST + t) * NC + c) * NFEAT + kk];
            sX2[(c * DD + 2 + kk) * BT + b] = v;
            sXL[c * 64 + lidx(2 + kk, b)]   = v;
        }
        for (int e = tid; e < NC * BT; e += TPB) {
            int c = e >> 2, b = e & 3;
            float v = sXN[c * BT + b];
            sX2[(c * DD + 1) * BT + b] = v;
            sXL[c * 64 + lidx(1, b)]   = v;
        }
        __syncthreads();

        // ============ Phase 2: gated graph MLP (4-way c-split chains) ============
        if (tid < NC) {
            const int j = tid;
            u64 A0 = pk2(b_mlp[j]), A1 = 0, A2 = 0, A3 = 0;
            u64 B0 = A0, B1 = 0, B2 = 0, B3 = 0;
            const float* wbase = W_mlp + j;
            for (int c = 0; c < NC; c += 4) {
#pragma unroll
                for (int p = 0; p < 4; ++p) {
                    const ulonglong2* xp = (const ulonglong2*)(sX2 + ((c + p) * DD + 1) * BT);
                    const float* wp = wbase + (size_t)(c + p) * IND * NC;
#pragma unroll
                    for (int kk = 0; kk < IND; ++kk) {
                        u64 w = pk2(wp[(size_t)kk * NC]);
                        ulonglong2 xv = xp[kk];
                        if (p == 0) { ffma2(A0, xv.x, w); ffma2(B0, xv.y, w); }
                        if (p == 1) { ffma2(A1, xv.x, w); ffma2(B1, xv.y, w); }
                        if (p == 2) { ffma2(A2, xv.x, w); ffma2(B2, xv.y, w); }
                        if (p == 3) { ffma2(A3, xv.x, w); ffma2(B3, xv.y, w); }
                    }
                }
            }
            float2 v01 = unpk(addx2(addx2(A0, A1), addx2(A2, A3)));
            float2 v23 = unpk(addx2(addx2(B0, B1), addx2(B2, B3)));
            float g0 = sigf(v01.x), g1 = sigf(v01.y);
            float g2 = sigf(v23.x), g3 = sigf(v23.y);
            sX2[(j * DD) * BT + 0] = g0;
            sX2[(j * DD) * BT + 1] = g1;
            sX2[(j * DD) * BT + 2] = g2;
            sX2[(j * DD) * BT + 3] = g3;
            sXL[j * 64 + lidx(0, 0)] = g0;
            sXL[j * 64 + lidx(0, 1)] = g1;
            sXL[j * 64 + lidx(0, 2)] = g2;
            sXL[j * 64 + lidx(0, 3)] = g3;
        }
        __syncthreads();

        // ============ Phase 3: GRU cell ============
        for (int e = tid; e < BT * DD; e += TPB) {
            int b = e / DD, k = e - b * DD;
            float s = 0.0f;
            for (int c = 0; c < NC; ++c) s += sX2[(c * DD + k) * BT + b];
            sU[b * 16 + k] = s * (1.0f / NC);
        }
        __syncthreads();
        for (int e = tid; e < BT * 96; e += TPB) {
            int b = e / 96, j = e - b * 96;
            float a = b_ih_g[j];
#pragma unroll
            for (int k = 0; k < DD; ++k)
                a = fmaf(sU[b * 16 + k], Wih_g[k * 96 + j], a);
            sGX[e] = a;
        }
        for (int e = tid; e < 16 * 96; e += TPB) {
            int lb = e / 96, j = e - lb * 96;
            int l = lb >> 2, b = lb & 3;
            float a = b_hh_g[j];
#pragma unroll
            for (int k = 0; k < HH; ++k)
                a = fmaf(sH[l * 128 + lidx(k, b)], Whh_g[k * 96 + j], a);
            sGH[e] = a;
        }
        __syncthreads();
        for (int e = tid; e < 4 * BT * HH; e += TPB) {
            int l = e >> 7, b = (e >> 5) & 3, j = e & 31;
            int gb = b * 96, ghb = (l * BT + b) * 96;
            float r = sigf(sGX[gb + j]      + sGH[ghb + j]);
            float z = sigf(sGX[gb + 32 + j] + sGH[ghb + 32 + j]);
            float n = tanha(sGX[gb + 64 + j] + r * sGH[ghb + 64 + j]);
            int hi = l * 128 + lidx(j, b);
            sH[hi] = (1.0f - z) * n + z * sH[hi];
        }
        __syncthreads();

        // ============ Phase 4: BiLSTM layer 0 (4-row x 1-batch, pre-activated) ====
        {
            int zr; asm volatile("mov.u32 %0, %1;" : "=r"(zr) : "r"(0));
            u64 W0X[4][8], W0H[4][16];
            float b0v[4];
#pragma unroll
            for (int i = 0; i < 4; ++i) {
                const int gr = dirg * 128 + r4 * 4 + i + zr;
#pragma unroll
                for (int p = 0; p < 7; ++p)
                    W0X[i][p] = pack2(Wih0[gr * DD + 2 * p], Wih0[gr * DD + 2 * p + 1]);
                W0X[i][7] = pack2(Wih0[gr * DD + 14], 0.0f);
                const u64* whp = (const u64*)(Whh0 + gr * HH);
#pragma unroll
                for (int p = 0; p < 16; ++p) W0H[i][p] = whp[p];
                b0v[i] = b0[gr];
            }

            for (int s = 0; s < NC; ++s) {
                const int city = dirg ? (NC - 1 - s) : s;
                u64 aA[4] = {0, 0, 0, 0};   // chain A: x-part + h[0..3]
                u64 aB[4] = {0, 0, 0, 0};   // chain B: h[4..7]
                const float* xb = sXL + city * 64 + bq * 4;
#pragma unroll
                for (int q = 0; q < 4; ++q) {
                    ulonglong2 xv = *(const ulonglong2*)(xb + q * 16);
#pragma unroll
                    for (int i = 0; i < 4; ++i) {
                        ffma2(aA[i], xv.x, W0X[i][2 * q]);
                        ffma2(aA[i], xv.y, W0X[i][2 * q + 1]);
                    }
                }
                const float* hb = sH + dirg * 128 + bq * 4;
#pragma unroll
                for (int q = 0; q < 8; ++q) {
                    ulonglong2 hv = *(const ulonglong2*)(hb + q * 16);
                    u64* tgt = (q < 4) ? aA : aB;
#pragma unroll
                    for (int i = 0; i < 4; ++i) {
                        ffma2(tgt[i], hv.x, W0H[i][2 * q]);
                        ffma2(tgt[i], hv.y, W0H[i][2 * q + 1]);
                    }
                }
                float4 av;
                {
                    float vv[4];
#pragma unroll
                    for (int i = 0; i < 4; ++i) {
                        float2 f = unpk(addx2(aA[i], aB[i]));
                        float raw = f.x + f.y + b0v[i];
                        vv[i] = isG0 ? tanha(raw) : sigf(raw);
                    }
                    av = make_float4(vv[0], vv[1], vv[2], vv[3]);
                }
                *(float4*)(sG + dirg * 512 + bq * 128 + r4 * 4) = av;
                dbar(dirg);
                {   // update: gates are pre-activated
                    const int cityu = dirg ? (NC - 1 - s) : s;
                    const float* g = sG + dirg * 512 + bu * 128;
                    float iv = g[ju], fv = g[32 + ju], gv = g[64 + ju], ov = g[96 + ju];
                    cL0 = fmaf(fv, cL0, iv * gv);
                    float hh2 = ov * tanha(cL0);
                    int hoff = lidx(ju, bu);
                    sH[dirg * 128 + hoff] = hh2;
                    if (dirg == 0)
                        gy0cta[(size_t)cityu * 128 + hoff] = hh2;
                    else
                        sY0B[cityu * 128 + hoff] = hh2;
                }
                dbar(dirg);
            }
        }
        __syncthreads();   // phase boundary: both dirs' y0 complete

        // ============ Phase 5: BiLSTM layer 1 (2-row x 2-batch, pre-activated) ====
        {
            int zr; asm volatile("mov.u32 %0, %1;" : "=r"(zr) : "r"(0));
            u64 W1X[2][32], W1H[2][16];
            float b1v[2];
#pragma unroll
            for (int i = 0; i < 2; ++i) {
                const int gr = dirg * 128 + r0 + i + zr;
                const u64* wx = (const u64*)(Wih1 + gr * 64);
#pragma unroll
                for (int p = 0; p < 32; ++p) W1X[i][p] = wx[p];
                const u64* wh = (const u64*)(Whh1 + gr * HH);
#pragma unroll
                for (int p = 0; p < 16; ++p) W1H[i][p] = wh[p];
                b1v[i] = b1[gr];
            }

            // prologue: stage y0f(0), prefetch y0f(1)
            {
                int c0_ = dirg ? (NC - 1) : 0;
                sXin[(dirg * 2 + 0) * 128 + loc] = gy0cta[(size_t)c0_ * 128 + loc];
            }
            float pf;
            {
                int c1_ = dirg ? (NC - 2) : 1;
                pf = gy0cta[(size_t)c1_ * 128 + loc];
            }
            dbar(dirg);
            int buf = 0;
            for (int s = 0; s < NC; ++s) {
                const int city = dirg ? (NC - 1 - s) : s;
                u64 aA[2][2] = {{0, 0}, {0, 0}};   // fb-part: y0f + h[0..3]
                u64 aB[2][2] = {{0, 0}, {0, 0}};   // y0b + h[4..7]
                const float* fb = sXin + (dirg * 2 + buf) * 128;
                const float* bb = sY0B + city * 128;
                const float* hb = sH + (2 + dirg) * 128;
#pragma unroll
                for (int q = 0; q < 8; ++q) {
#pragma unroll
                    for (int jb = 0; jb < 2; ++jb) {
                        ulonglong2 yv = *(const ulonglong2*)(fb + q * 16 + (2 * bh + jb) * 4);
                        ffma2(aA[0][jb], yv.x, W1X[0][2 * q]);
                        ffma2(aA[0][jb], yv.y, W1X[0][2 * q + 1]);
                        ffma2(aA[1][jb], yv.x, W1X[1][2 * q]);
                        ffma2(aA[1][jb], yv.y, W1X[1][2 * q + 1]);
                    }
                }
#pragma unroll
                for (int q = 0; q < 8; ++q) {
#pragma unroll
                    for (int jb = 0; jb < 2; ++jb) {
                        ulonglong2 bv = *(const ulonglong2*)(bb + q * 16 + (2 * bh + jb) * 4);
                        ffma2(aB[0][jb], bv.x, W1X[0][16 + 2 * q]);
                        ffma2(aB[0][jb], bv.y, W1X[0][16 + 2 * q + 1]);
                        ffma2(aB[1][jb], bv.x, W1X[1][16 + 2 * q]);
                        ffma2(aB[1][jb], bv.y, W1X[1][16 + 2 * q + 1]);
                    }
                }
#pragma unroll
                for (int q = 0; q < 8; ++q) {
                    u64* tgt0 = (q < 4) ? &aA[0][0] : &aB[0][0];
                    u64* tgt1 = (q < 4) ? &aA[1][0] : &aB[1][0];
#pragma unroll
                    for (int jb = 0; jb < 2; ++jb) {
                        ulonglong2 hv = *(const ulonglong2*)(hb + q * 16 + (2 * bh + jb) * 4);
                        ffma2(tgt0[jb], hv.x, W1H[0][2 * q]);
                        ffma2(tgt0[jb], hv.y, W1H[0][2 * q + 1]);
                        ffma2(tgt1[jb], hv.x, W1H[1][2 * q]);
                        ffma2(tgt1[jb], hv.y, W1H[1][2 * q + 1]);
                    }
                }
#pragma unroll
                for (int jb = 0; jb < 2; ++jb) {
                    float2 f0 = unpk(addx2(aA[0][jb], aB[0][jb]));
                    float2 f1 = unpk(addx2(aA[1][jb], aB[1][jb]));
                    float raw0 = f0.x + f0.y + b1v[0];
                    float raw1 = f1.x + f1.y + b1v[1];
                    float a0 = isG1 ? tanha(raw0) : sigf(raw0);
                    float a1 = isG1 ? tanha(raw1) : sigf(raw1);
                    *(float2*)(sG + dirg * 512 + (2 * bh + jb) * 128 + r0) =
                        make_float2(a0, a1);
                }
                dbar(dirg);
                // window: stash y0f(s+1), update, prefetch y0f(s+2)
                if (s + 1 < NC)
                    sXin[(dirg * 2 + (buf ^ 1)) * 128 + loc] = pf;
                {
                    const float* g = sG + dirg * 512 + bu * 128;
                    float iv = g[ju], fv = g[32 + ju], gv = g[64 + ju], ov = g[96 + ju];
                    cL1 = fmaf(fv, cL1, iv * gv);
                    float hh2 = ov * tanha(cL1);
                    sH[(2 + dirg) * 128 + lidx(ju, bu)] = hh2;
                    if (dirg == 0) {
                        // inline FC head (fwd half only)
                        float v = wfc * hh2;
                        v += __shfl_xor_sync(0xffffffffu, v, 16);
                        v += __shfl_xor_sync(0xffffffffu, v, 8);
                        v += __shfl_xor_sync(0xffffffffu, v, 4);
                        v += __shfl_xor_sync(0xffffffffu, v, 2);
                        v += __shfl_xor_sync(0xffffffffu, v, 1);
                        if (ju == 0) {
                            float a = v + bfc;
                            sXN[s * BT + bu] = a;
                            out[((size_t)(bg + bu) * NPRED + t) * NC + s] = a;
                        }
                    }
                }
                if (s + 2 < NC) {
                    int cp = dirg ? (NC - 3 - s) : (s + 2);
                    pf = gy0cta[(size_t)cp * 128 + loc];
                }
                dbar(dirg);
                buf ^= 1;
            }
        }
        __syncthreads();
    }
}

extern "C" void kernel_launch(void* const* d_in, const int* in_sizes, int n_in,
                              void* d_out, int out_size) {
    (void)in_sizes; (void)n_in; (void)out_size;
    const float* rain_hist = (const float*)d_in[0];
    const float* feature   = (const float*)d_in[1];
    const float* h0        = (const float*)d_in[2];
    const float* c0        = (const float*)d_in[3];
    const float* W_mlp     = (const float*)d_in[4];
    const float* b_mlp     = (const float*)d_in[5];
    const float* Wih_g     = (const float*)d_in[6];
    const float* Whh_g     = (const float*)d_in[7];
    const float* b_ih_g    = (const float*)d_in[8];
    const float* b_hh_g    = (const float*)d_in[9];
    const float* Wih0      = (const float*)d_in[10];
    const float* Whh0      = (const float*)d_in[11];
    const float* b0        = (const float*)d_in[12];
    const float* Wih1      = (const float*)d_in[13];
    const float* Whh1      = (const float*)d_in[14];
    const float* b1        = (const float*)d_in[15];
    const float* W_fc      = (const float*)d_in[16];
    const float* b_fc      = (const float*)d_in[17];

    size_t smem = (size_t)SMEM_FLOATS * sizeof(float);
    cudaFuncSetAttribute(bilstm_kernel,
                         cudaFuncAttributeMaxDynamicSharedMemorySize, (int)smem);

    bilstm_kernel<<<NCTA, TPB, smem>>>(
        rain_hist, feature, h0, c0, W_mlp, b_mlp,
        Wih_g, Whh_g, b_ih_g, b_hh_g,
        Wih0, Whh0, b0, Wih1, Whh1, b1,
        W_fc, b_fc, (float*)d_out);
}

// round 16
// speedup vs baseline: 1.1978x; 1.1978x over previous
#include <cuda_runtime.h>

// Problem constants
#define NCTA   128
#define TPB    256
#define NB     512
#define BT     4       // batch elements per CTA
#define NC     184     // cities
#define HH     32      // hidden
#define IND    14      // in_dim
#define DD     15      // in_dim + 1
#define NPRED  24
#define NHIST  24
#define NFEAT  13      // in_dim - 1
#define FTOT   48      // hist + pred

// Global scratch (per-CTA private; [city][q][b][dk] layout, 128 f/city)
__device__ float g_y0[(size_t)NCTA * NC * 128];
__device__ float g_y1[(size_t)NCTA * NC * 128];

// Shared memory layout (float offsets)
#define OFF_X2   0        // 184*15*4 = 11040  x tile OLD layout [c][k15][b] (MLP/GRU)
#define OFF_XL   11040    // 184*64   = 11776  x tile LSTM layout [c][q4][b][dk]
#define OFF_Y0B  22816    // 184*128  = 23552  bwd y0 [c][q8][b][dk]
#define OFF_XIN  46368    // 2dir*2buf*128     staged fwd y0 [q8][b][dk]
#define OFF_G    46880    // 2*4*128  = 1024   raw gates [dir][b][row]
#define OFF_H    47904    // 4ld*128  = 512    h state [ld][q8][b][dk]
#define OFF_XN   48416    // 184*4    = 736
#define OFF_GX   49152    // 384
#define OFF_GH   49536    // 1536
#define OFF_U    51072    // 64
#define SMEM_FLOATS 51136 // 204,544 bytes

typedef unsigned long long u64;

__device__ __forceinline__ u64 pk2(float w) {
    u64 r; asm("mov.b64 %0, {%1, %1};" : "=l"(r) : "f"(w)); return r;
}
__device__ __forceinline__ u64 pack2(float a, float b) {
    u64 r; asm("mov.b64 %0, {%1, %2};" : "=l"(r) : "f"(a), "f"(b)); return r;
}
__device__ __forceinline__ void ffma2(u64& a, u64 x, u64 w) {
    asm("fma.rn.f32x2 %0, %1, %2, %0;" : "+l"(a) : "l"(x), "l"(w));
}
__device__ __forceinline__ u64 addx2(u64 a, u64 b) {
    u64 r; asm("add.rn.f32x2 %0, %1, %2;" : "=l"(r) : "l"(a), "l"(b)); return r;
}
__device__ __forceinline__ float2 unpk(u64 a) {
    float2 f; asm("mov.b64 {%0, %1}, %2;" : "=f"(f.x), "=f"(f.y) : "l"(a)); return f;
}
__device__ __forceinline__ float tanha(float x) {
    float r; asm("tanh.approx.f32 %0, %1;" : "=f"(r) : "f"(x)); return r;
}
__device__ __forceinline__ float sigf(float x) {
    return fmaf(0.5f, tanha(0.5f * x), 0.5f);
}
// per-direction named barrier (128 threads)
__device__ __forceinline__ void dbar(int dir) {
    asm volatile("bar.sync %0, %1;" :: "r"(1 + dir), "r"(128) : "memory");
}

// LSTM-layout index: k -> quad/byte position for batch b
__device__ __forceinline__ int lidx(int k, int b) {
    return (k >> 2) * 16 + b * 4 + (k & 3);
}

__global__ void __launch_bounds__(TPB, 1)
bilstm_kernel(const float* __restrict__ rain_hist,
              const float* __restrict__ feature,
              const float* __restrict__ h0,
              const float* __restrict__ c0,
              const float* __restrict__ W_mlp,
              const float* __restrict__ b_mlp,
              const float* __restrict__ Wih_g,
              const float* __restrict__ Whh_g,
              const float* __restrict__ b_ih_g,
              const float* __restrict__ b_hh_g,
              const float* __restrict__ Wih0,
              const float* __restrict__ Whh0,
              const float* __restrict__ b0,
              const float* __restrict__ Wih1,
              const float* __restrict__ Whh1,
              const float* __restrict__ b1,
              const float* __restrict__ W_fc,
              const float* __restrict__ b_fc,
              float* __restrict__ out)
{
    extern __shared__ float sm[];
    float* sX2  = sm + OFF_X2;
    float* sXL  = sm + OFF_XL;
    float* sY0B = sm + OFF_Y0B;
    float* sXin = sm + OFF_XIN;
    float* sG   = sm + OFF_G;
    float* sH   = sm + OFF_H;
    float* sXN  = sm + OFF_XN;
    float* sGX  = sm + OFF_GX;
    float* sGH  = sm + OFF_GH;
    float* sU   = sm + OFF_U;

    const int tid = threadIdx.x;
    const int cta = blockIdx.x;
    const int bg  = cta * BT;

    // gate-phase mapping: 2 rows x 2 batches per thread
    const int dirg = tid >> 7;          // direction
    const int bh   = tid & 1;           // batch half (b in {2bh, 2bh+1})
    const int rp   = (tid >> 1) & 63;   // row pair
    const int r0   = rp * 2;            // rows r0, r0+1 within dir
    // update-phase mapping
    const int bu   = (tid >> 5) & 3;
    const int ju   = tid & 31;
    const int loc  = tid & 127;

    // c-state in update-thread registers
    float cL0 = c0[((size_t)dirg * NB + bg + bu) * HH + ju];
    float cL1 = c0[((size_t)(2 + dirg) * NB + bg + bu) * HH + ju];

    // ---- initial h, xn, pad slot ----
    for (int e = tid; e < 4 * HH * BT; e += TPB) {
        int ld = e >> 7, k = (e >> 2) & 31, b = e & 3;
        sH[ld * 128 + lidx(k, b)] = h0[((size_t)ld * NB + bg + b) * HH + k];
    }
    for (int e = tid; e < NC * BT; e += TPB) {
        int c = e >> 2, b = e & 3;
        sXN[c * BT + b] = rain_hist[((size_t)(bg + b) * NHIST + (NHIST - 1)) * NC + c];
        sXL[c * 64 + lidx(15, b)] = 0.0f;    // zero pad, never overwritten
    }
    __syncthreads();

    float* gy0cta = g_y0 + (size_t)cta * NC * 128;
    float* gy1cta = g_y1 + (size_t)cta * NC * 128;

    for (int t = 0; t < NPRED; ++t) {
        // ============ Phase 1: build both x tiles ============
        for (int e = tid; e < NC * NFEAT * BT; e += TPB) {
            int b = e / (NC * NFEAT);
            int rem = e - b * (NC * NFEAT);
            int c = rem / NFEAT;
            int kk = rem - c * NFEAT;
            float v = feature[(((size_t)(bg + b) * FTOT + NHIST + t) * NC + c) * NFEAT + kk];
            sX2[(c * DD + 2 + kk) * BT + b] = v;
            sXL[c * 64 + lidx(2 + kk, b)]   = v;
        }
        for (int e = tid; e < NC * BT; e += TPB) {
            int c = e >> 2, b = e & 3;
            float v = sXN[c * BT + b];
            sX2[(c * DD + 1) * BT + b] = v;
            sXL[c * 64 + lidx(1, b)]   = v;
        }
        __syncthreads();

        // ============ Phase 2: gated graph MLP (4-way c-split chains) ============
        if (tid < NC) {
            const int j = tid;
            u64 A0 = pk2(b_mlp[j]), A1 = 0, A2 = 0, A3 = 0;
            u64 B0 = A0, B1 = 0, B2 = 0, B3 = 0;
            const float* wbase = W_mlp + j;
            for (int c = 0; c < NC; c += 4) {
#pragma unroll
                for (int p = 0; p < 4; ++p) {
                    const ulonglong2* xp = (const ulonglong2*)(sX2 + ((c + p) * DD + 1) * BT);
                    const float* wp = wbase + (size_t)(c + p) * IND * NC;
#pragma unroll
                    for (int kk = 0; kk < IND; ++kk) {
                        u64 w = pk2(wp[(size_t)kk * NC]);
                        ulonglong2 xv = xp[kk];
                        if (p == 0) { ffma2(A0, xv.x, w); ffma2(B0, xv.y, w); }
                        if (p == 1) { ffma2(A1, xv.x, w); ffma2(B1, xv.y, w); }
                        if (p == 2) { ffma2(A2, xv.x, w); ffma2(B2, xv.y, w); }
                        if (p == 3) { ffma2(A3, xv.x, w); ffma2(B3, xv.y, w); }
                    }
                }
            }
            float2 v01 = unpk(addx2(addx2(A0, A1), addx2(A2, A3)));
            float2 v23 = unpk(addx2(addx2(B0, B1), addx2(B2, B3)));
            float g0 = sigf(v01.x), g1 = sigf(v01.y);
            float g2 = sigf(v23.x), g3 = sigf(v23.y);
            sX2[(j * DD) * BT + 0] = g0;
            sX2[(j * DD) * BT + 1] = g1;
            sX2[(j * DD) * BT + 2] = g2;
            sX2[(j * DD) * BT + 3] = g3;
            sXL[j * 64 + lidx(0, 0)] = g0;
            sXL[j * 64 + lidx(0, 1)] = g1;
            sXL[j * 64 + lidx(0, 2)] = g2;
            sXL[j * 64 + lidx(0, 3)] = g3;
        }
        __syncthreads();

        // ============ Phase 3: GRU cell ============
        for (int e = tid; e < BT * DD; e += TPB) {
            int b = e / DD, k = e - b * DD;
            float s = 0.0f;
            for (int c = 0; c < NC; ++c) s += sX2[(c * DD + k) * BT + b];
            sU[b * 16 + k] = s * (1.0f / NC);
        }
        __syncthreads();
        for (int e = tid; e < BT * 96; e += TPB) {
            int b = e / 96, j = e - b * 96;
            float a = b_ih_g[j];
#pragma unroll
            for (int k = 0; k < DD; ++k)
                a = fmaf(sU[b * 16 + k], Wih_g[k * 96 + j], a);
            sGX[e] = a;
        }
        for (int e = tid; e < 16 * 96; e += TPB) {
            int lb = e / 96, j = e - lb * 96;
            int l = lb >> 2, b = lb & 3;
            float a = b_hh_g[j];
#pragma unroll
            for (int k = 0; k < HH; ++k)
                a = fmaf(sH[l * 128 + lidx(k, b)], Whh_g[k * 96 + j], a);
            sGH[e] = a;
        }
        __syncthreads();
        for (int e = tid; e < 4 * BT * HH; e += TPB) {
            int l = e >> 7, b = (e >> 5) & 3, j = e & 31;
            int gb = b * 96, ghb = (l * BT + b) * 96;
            float r = sigf(sGX[gb + j]      + sGH[ghb + j]);
            float z = sigf(sGX[gb + 32 + j] + sGH[ghb + 32 + j]);
            float n = tanha(sGX[gb + 64 + j] + r * sGH[ghb + 64 + j]);
            int hi = l * 128 + lidx(j, b);
            sH[hi] = (1.0f - z) * n + z * sH[hi];
        }
        __syncthreads();

        // ============ Phase 4: BiLSTM layer 0 (split chains, per-dir barriers) ====
        {
            int zr; asm volatile("mov.u32 %0, %1;" : "=r"(zr) : "r"(0));
            u64 W0X[2][8], W0H[2][16];
            float b0v[2];
#pragma unroll
            for (int i = 0; i < 2; ++i) {
                const int gr = dirg * 128 + r0 + i + zr;
#pragma unroll
                for (int p = 0; p < 7; ++p)
                    W0X[i][p] = pack2(Wih0[gr * DD + 2 * p], Wih0[gr * DD + 2 * p + 1]);
                W0X[i][7] = pack2(Wih0[gr * DD + 14], 0.0f);
                const u64* whp = (const u64*)(Whh0 + gr * HH);
#pragma unroll
                for (int p = 0; p < 16; ++p) W0H[i][p] = whp[p];
                b0v[i] = b0[gr];
            }

            for (int s = 0; s < NC; ++s) {
                const int city = dirg ? (NC - 1 - s) : s;
                u64 aA[2][2] = {{0, 0}, {0, 0}};   // chain A: x-part + h[0..3]
                u64 aB[2][2] = {{0, 0}, {0, 0}};   // chain B: h[4..7]
                const float* xb = sXL + city * 64;
#pragma unroll
                for (int q = 0; q < 4; ++q) {
#pragma unroll
                    for (int jb = 0; jb < 2; ++jb) {
                        ulonglong2 xv = *(const ulonglong2*)(xb + q * 16 + (2 * bh + jb) * 4);
                        ffma2(aA[0][jb], xv.x, W0X[0][2 * q]);
                        ffma2(aA[0][jb], xv.y, W0X[0][2 * q + 1]);
                        ffma2(aA[1][jb], xv.x, W0X[1][2 * q]);
                        ffma2(aA[1][jb], xv.y, W0X[1][2 * q + 1]);
                    }
                }
                const float* hb = sH + dirg * 128;
#pragma unroll
                for (int q = 0; q < 8; ++q) {
                    u64* tgt0 = (q < 4) ? &aA[0][0] : &aB[0][0];
                    u64* tgt1 = (q < 4) ? &aA[1][0] : &aB[1][0];
#pragma unroll
                    for (int jb = 0; jb < 2; ++jb) {
                        ulonglong2 hv = *(const ulonglong2*)(hb + q * 16 + (2 * bh + jb) * 4);
                        ffma2(tgt0[jb], hv.x, W0H[0][2 * q]);
                        ffma2(tgt0[jb], hv.y, W0H[0][2 * q + 1]);
                        ffma2(tgt1[jb], hv.x, W0H[1][2 * q]);
                        ffma2(tgt1[jb], hv.y, W0H[1][2 * q + 1]);
                    }
                }
#pragma unroll
                for (int i = 0; i < 2; ++i)
#pragma unroll
                    for (int jb = 0; jb < 2; ++jb) {
                        float2 f = unpk(addx2(aA[i][jb], aB[i][jb]));
                        sG[dirg * 512 + (2 * bh + jb) * 128 + r0 + i] = f.x + f.y + b0v[i];
                    }
                dbar(dirg);
                {   // update (du == dirg by construction)
                    const int cityu = dirg ? (NC - 1 - s) : s;
                    const float* g = sG + dirg * 512 + bu * 128;
                    float iv = sigf(g[ju]);
                    float fv = sigf(g[32 + ju]);
                    float gv = tanha(g[64 + ju]);
                    float ov = sigf(g[96 + ju]);
                    cL0 = fmaf(fv, cL0, iv * gv);
                    float hh2 = ov * tanha(cL0);
                    int hoff = lidx(ju, bu);
                    sH[dirg * 128 + hoff] = hh2;
                    if (dirg == 0)
                        gy0cta[(size_t)cityu * 128 + hoff] = hh2;
                    else
                        sY0B[cityu * 128 + hoff] = hh2;
                }
                dbar(dirg);
            }
        }
        __syncthreads();   // phase boundary: both dirs' y0 complete

        // ============ Phase 5: BiLSTM layer 1 (split chains, per-dir barriers) ====
        {
            int zr; asm volatile("mov.u32 %0, %1;" : "=r"(zr) : "r"(0));
            u64 W1X[2][32], W1H[2][16];
            float b1v[2];
#pragma unroll
            for (int i = 0; i < 2; ++i) {
                const int gr = dirg * 128 + r0 + i + zr;
                const u64* wx = (const u64*)(Wih1 + gr * 64);
#pragma unroll
                for (int p = 0; p < 32; ++p) W1X[i][p] = wx[p];
                const u64* wh = (const u64*)(Whh1 + gr * HH);
#pragma unroll
                for (int p = 0; p < 16; ++p) W1H[i][p] = wh[p];
                b1v[i] = b1[gr];
            }

            // prologue: stage y0f(0), prefetch y0f(1)
            {
                int c0_ = dirg ? (NC - 1) : 0;
                sXin[(dirg * 2 + 0) * 128 + loc] = gy0cta[(size_t)c0_ * 128 + loc];
            }
            float pf;
            {
                int c1_ = dirg ? (NC - 2) : 1;
                pf = gy0cta[(size_t)c1_ * 128 + loc];
            }
            dbar(dirg);
            int buf = 0;
            for (int s = 0; s < NC; ++s) {
                const int city = dirg ? (NC - 1 - s) : s;
                u64 aA[2][2] = {{0, 0}, {0, 0}};   // fb-part: y0f + h[0..3]
                u64 aB[2][2] = {{0, 0}, {0, 0}};   // y0b + h[4..7]
                const float* fb = sXin + (dirg * 2 + buf) * 128;
                const float* bb = sY0B + city * 128;
                const float* hb = sH + (2 + dirg) * 128;
#pragma unroll
                for (int q = 0; q < 8; ++q) {
#pragma unroll
                    for (int jb = 0; jb < 2; ++jb) {
                        ulonglong2 yv = *(const ulonglong2*)(fb + q * 16 + (2 * bh + jb) * 4);
                        ffma2(aA[0][jb], yv.x, W1X[0][2 * q]);
                        ffma2(aA[0][jb], yv.y, W1X[0][2 * q + 1]);
                        ffma2(aA[1][jb], yv.x, W1X[1][2 * q]);
                        ffma2(aA[1][jb], yv.y, W1X[1][2 * q + 1]);
                    }
                }
#pragma unroll
                for (int q = 0; q < 8; ++q) {
#pragma unroll
                    for (int jb = 0; jb < 2; ++jb) {
                        ulonglong2 bv = *(const ulonglong2*)(bb + q * 16 + (2 * bh + jb) * 4);
                        ffma2(aB[0][jb], bv.x, W1X[0][16 + 2 * q]);
                        ffma2(aB[0][jb], bv.y, W1X[0][16 + 2 * q + 1]);
                        ffma2(aB[1][jb], bv.x, W1X[1][16 + 2 * q]);
                        ffma2(aB[1][jb], bv.y, W1X[1][16 + 2 * q + 1]);
                    }
                }
#pragma unroll
                for (int q = 0; q < 8; ++q) {
                    u64* tgt0 = (q < 4) ? &aA[0][0] : &aB[0][0];
                    u64* tgt1 = (q < 4) ? &aA[1][0] : &aB[1][0];
#pragma unroll
                    for (int jb = 0; jb < 2; ++jb) {
                        ulonglong2 hv = *(const ulonglong2*)(hb + q * 16 + (2 * bh + jb) * 4);
                        ffma2(tgt0[jb], hv.x, W1H[0][2 * q]);
                        ffma2(tgt0[jb], hv.y, W1H[0][2 * q + 1]);
                        ffma2(tgt1[jb], hv.x, W1H[1][2 * q]);
                        ffma2(tgt1[jb], hv.y, W1H[1][2 * q + 1]);
                    }
                }
#pragma unroll
                for (int i = 0; i < 2; ++i)
#pragma unroll
                    for (int jb = 0; jb < 2; ++jb) {
                        float2 f = unpk(addx2(aA[i][jb], aB[i][jb]));
                        sG[dirg * 512 + (2 * bh + jb) * 128 + r0 + i] = f.x + f.y + b1v[i];
                    }
                dbar(dirg);
                // window: stash y0f(s+1), update, prefetch y0f(s+2)
                if (s + 1 < NC)
                    sXin[(dirg * 2 + (buf ^ 1)) * 128 + loc] = pf;
                {
                    const float* g = sG + dirg * 512 + bu * 128;
                    float iv = sigf(g[ju]);
                    float fv = sigf(g[32 + ju]);
                    float gv = tanha(g[64 + ju]);
                    float ov = sigf(g[96 + ju]);
                    cL1 = fmaf(fv, cL1, iv * gv);
                    float hh2 = ov * tanha(cL1);
                    int hoff = lidx(ju, bu);
                    sH[(2 + dirg) * 128 + hoff] = hh2;
                    if (dirg == 0)  // forward y1 consumed by FC head (Phase 6)
                        gy1cta[(size_t)s * 128 + hoff] = hh2;
                }
                if (s + 2 < NC) {
                    int cp = dirg ? (NC - 3 - s) : (s + 2);
                    pf = gy0cta[(size_t)cp * 128 + loc];
                }
                dbar(dirg);
                buf ^= 1;
            }
        }
        __syncthreads();   // all dir0 y1 STGs visible CTA-wide

        // ============ Phase 6: FC head (parallel, off the recurrence) ============
        {
            const float bfc = b_fc[0];
            for (int e = tid; e < NC * BT; e += TPB) {
                int c = e >> 2, b = e & 3;
                const float* yp = gy1cta + (size_t)c * 128 + b * 4;
                float a = bfc;
#pragma unroll
                for (int q = 0; q < 8; ++q) {
                    float4 y = *(const float4*)(yp + q * 16);
                    float4 w = *(const float4*)(W_fc + q * 4);
                    a = fmaf(y.x, w.x, a); a = fmaf(y.y, w.y, a);
                    a = fmaf(y.z, w.z, a); a = fmaf(y.w, w.w, a);
                }
                sXN[c * BT + b] = a;
                out[((size_t)(bg + b) * NPRED + t) * NC + c] = a;
            }
        }
        __syncthreads();
    }
}

extern "C" void kernel_launch(void* const* d_in, const int* in_sizes, int n_in,
                              void* d_out, int out_size) {
    (void)in_sizes; (void)n_in; (void)out_size;
    const float* rain_hist = (const float*)d_in[0];
    const float* feature   = (const float*)d_in[1];
    const float* h0        = (const float*)d_in[2];
    const float* c0        = (const float*)d_in[3];
    const float* W_mlp     = (const float*)d_in[4];
    const float* b_mlp     = (const float*)d_in[5];
    const float* Wih_g     = (const float*)d_in[6];
    const float* Whh_g     = (const float*)d_in[7];
    const float* b_ih_g    = (const float*)d_in[8];
    const float* b_hh_g    = (const float*)d_in[9];
    const float* Wih0      = (const float*)d_in[10];
    const float* Whh0      = (const float*)d_in[11];
    const float* b0        = (const float*)d_in[12];
    const float* Wih1      = (const float*)d_in[13];
    const float* Whh1      = (const float*)d_in[14];
    const float* b1        = (const float*)d_in[15];
    const float* W_fc      = (const float*)d_in[16];
    const float* b_fc      = (const float*)d_in[17];

    size_t smem = (size_t)SMEM_FLOATS * sizeof(float);
    cudaFuncSetAttribute(bilstm_kernel,
                         cudaFuncAttributeMaxDynamicSharedMemorySize, (int)smem);

    bilstm_kernel<<<NCTA, TPB, smem>>>(
        rain_hist, feature, h0, c0, W_mlp, b_mlp,
        Wih_g, Whh_g, b_ih_g, b_hh_g,
        Wih0, Whh0, b0, Wih1, Whh1, b1,
        W_fc, b_fc, (float*)d_out);
}